// round 15
// baseline (speedup 1.0000x reference)
#include <cuda_runtime.h>

// mLSTM cell: B=512, T=256, I=7, H=64, fp32.
// Grid 128 x block 256: 4 independent batches ("groups" of 64 threads = 2
// warps) per CTA. Thread j of a group owns full state row C~[j,0..63] as 32
// f32x2 register pairs + channel j's gates.
// Two-phase chunked schedule, Tc=16 (== rescale window):
//   Phase B: 16 steps of gate math back-to-back (no barriers), a/q~ and
//            packed (o,rden) -> smem, v -> registers.
//   Phase C: 16 steps of C-update/num/h back-to-back (no barriers).
// 3 barriers per chunk x 16 chunks = 48 barriers total (vs 96 in Tc=8).
// o/rden live in smem (packed u64, per-thread slot) to free ~32 registers ->
// ptxas hoisting/scheduling headroom in Phase C (the R14 lesson: at 254 regs
// nothing can be interleaved).
// Factored state: C = F (per-col) * C~ ; C~ += a (x) v, a = ik/F;
// num[r] = sum_c q~[c]*C~[r,c], q~ = F*q (exact). Rescale at chunk end.
// Transcendentals folded: i=ex2(log2e*z), f=rcp(1+ex2(-log2e*z)),
// o=0.5*tanh+0.5, h-tanh=tanh.approx, den via rcp.
// Sq(t)=sum_r q_t[r] as a linear form (row-summed Wq,bq) -> thread-local den.
// n row-uniform (n0==0): n[r,c] = Ftot[c]*n0[r,c] + m[c] (general form kept).
// Dynamic smem (~67KB) since static cap is 48KB.

#define NB 512
#define NT 256
#define NI 7
#define NH 64
#define GROUPS 4
#define NTH (NH * GROUPS)      // 256
#define NGRID (NB / GROUPS)    // 128
#define TC 16
#define NC (NT / TC)           // 16 chunks
#define L2E 1.4426950408889634f

typedef unsigned long long u64;

// dynamic smem layout (floats):
//   a_s  : [GROUPS][TC][NH]            4096
//   q_s  : [GROUPS][TC][NH]            4096
//   od_s : [GROUPS][TC][NH] u64        8192 (floats)
//   xs   : [GROUPS][TC*8]              512
//   Fsh  : [GROUPS][NH]                256
//   wqp  : [GROUPS][2][8]              64
#define OFF_A   0
#define OFF_Q   (OFF_A + GROUPS * TC * NH)
#define OFF_OD  (OFF_Q + GROUPS * TC * NH)
#define OFF_XS  (OFF_OD + GROUPS * TC * NH * 2)
#define OFF_FSH (OFF_XS + GROUPS * TC * 8)
#define OFF_WQP (OFF_FSH + GROUPS * NH)
#define SMEM_FLOATS (OFF_WQP + GROUPS * 16)
#define SMEM_BYTES (SMEM_FLOATS * 4)

__device__ __forceinline__ u64 pk2(float lo, float hi) {
    u64 r; asm("mov.b64 %0, {%1,%2};" : "=l"(r) : "f"(lo), "f"(hi)); return r;
}
__device__ __forceinline__ void upk2(u64 a, float& lo, float& hi) {
    asm("mov.b64 {%0,%1}, %2;" : "=f"(lo), "=f"(hi) : "l"(a));
}
__device__ __forceinline__ u64 fma2(u64 a, u64 b, u64 c) {
    u64 d; asm("fma.rn.f32x2 %0, %1, %2, %3;" : "=l"(d) : "l"(a), "l"(b), "l"(c)); return d;
}
__device__ __forceinline__ u64 mul2(u64 a, u64 b) {
    u64 d; asm("mul.rn.f32x2 %0, %1, %2;" : "=l"(d) : "l"(a), "l"(b)); return d;
}
__device__ __forceinline__ u64 add2(u64 a, u64 b) {
    u64 d; asm("add.rn.f32x2 %0, %1, %2;" : "=l"(d) : "l"(a), "l"(b)); return d;
}
__device__ __forceinline__ float ex2f(float a)  { float r; asm("ex2.approx.f32 %0, %1;"  : "=f"(r) : "f"(a)); return r; }
__device__ __forceinline__ float rcpf(float a)  { float r; asm("rcp.approx.f32 %0, %1;"  : "=f"(r) : "f"(a)); return r; }
__device__ __forceinline__ float tanhap(float a){ float r; asm("tanh.approx.f32 %0, %1;" : "=f"(r) : "f"(a)); return r; }
__device__ __forceinline__ void gbar(int g) {
    asm volatile("bar.sync %0, 64;" :: "r"(g + 1) : "memory");
}

__global__ __launch_bounds__(NTH) void mlstm_kernel(
    const float* __restrict__ x,  const float* __restrict__ C0, const float* __restrict__ n0,
    const float* __restrict__ Wq, const float* __restrict__ bq,
    const float* __restrict__ Wk, const float* __restrict__ bk,
    const float* __restrict__ Wv, const float* __restrict__ bv,
    const float* __restrict__ Wi, const float* __restrict__ bi,
    const float* __restrict__ Wf, const float* __restrict__ bf,
    const float* __restrict__ Wo, const float* __restrict__ bo,
    float* __restrict__ out)
{
    extern __shared__ __align__(16) float smem[];
    const int g = threadIdx.x >> 6;      // group (batch slot) 0..3
    const int j = threadIdx.x & 63;      // row / gate channel within group
    const int b = blockIdx.x * GROUPS + g;

    float* a_s  = smem + OFF_A  + g * (TC * NH);
    float* q_s  = smem + OFF_Q  + g * (TC * NH);
    u64*   od_s = (u64*)(smem + OFF_OD) + g * (TC * NH);
    float* xsg  = smem + OFF_XS + g * (TC * 8);
    float* Fsh  = smem + OFF_FSH + g * NH;
    float* wqp  = smem + OFF_WQP + g * 16;

    const float* xb = x + (size_t)b * NT * NI;
    // chunk element e (0..111): slot=(e/7)*8 + e%7 ; e and e+56 -> slot, slot+64
    const int xslot = (j / 7) * 8 + (j % 7);

    // --- packed gate weights for channel j, folded constants ---
    // wqk: (Wq, 0.125*Wk)   wvi: (Wv, log2e*Wi)   wfo: (-log2e*Wf, 0.5*Wo)
    u64 wqk[NI], wvi[NI], wfo[NI];
    float p[8];
#pragma unroll
    for (int i = 0; i < NI; i++) {
        float wq = Wq[j * NI + i];
        p[i]   = wq;
        wqk[i] = pk2(wq, 0.125f * Wk[j * NI + i]);
        wvi[i] = pk2(Wv[j * NI + i],  L2E * Wi[j * NI + i]);
        wfo[i] = pk2(-L2E * Wf[j * NI + i], 0.5f * Wo[j * NI + i]);
    }
    p[7] = bq[j];
    const u64 bqk = pk2(bq[j], 0.125f * bk[j]);
    const u64 bvi = pk2(bv[j],  L2E * bi[j]);
    const u64 bfo = pk2(-L2E * bf[j], 0.5f * bo[j]);

    // row-sum of Wq/bq over this group's 64 channels (warp reduce + combine)
#pragma unroll
    for (int off = 16; off; off >>= 1)
#pragma unroll
        for (int i = 0; i < 8; i++)
            p[i] += __shfl_xor_sync(0xffffffffu, p[i], off);
    if ((j & 31) == 0)
#pragma unroll
        for (int i = 0; i < 8; i++)
            wqp[(j >> 5) * 8 + i] = p[i];

    // --- prefetch first x chunk (112 floats; thread j<56 holds 2) ---
    float xpre0 = 0.f, xpre1 = 0.f;
    if (j < 56) { xpre0 = xb[j]; xpre1 = xb[56 + j]; }

    // --- C~ row j -> 32 packed pairs (init F=1 -> C~ = C0) ---
    u64 Creg[32];
    {
        const double2* cp = (const double2*)(C0 + (size_t)b * NH * NH + (size_t)j * NH);
#pragma unroll
        for (int gg = 0; gg < 16; gg++) {
            double2 d = cp[gg];
            Creg[2 * gg]     = __double_as_longlong(d.x);
            Creg[2 * gg + 1] = __double_as_longlong(d.y);
        }
    }

    gbar(g);   // wqp visible within group

    float wsq[NI], bsq;
#pragma unroll
    for (int i = 0; i < NI; i++) wsq[i] = wqp[i] + wqp[8 + i];
    bsq = wqp[7] + wqp[15];

    float F    = 1.f;   // running f-product within current chunk (channel j)
    float Ftot = 1.f;   // full product (for n output)
    float nv   = 0.f;   // m[j]: row-replicated n component

    float* outh = out + (size_t)b * NT * NH;
    float* outC = out + (size_t)NB * NT * NH + (size_t)b * NH * NH;
    float* outN = out + (size_t)NB * NT * NH + (size_t)NB * NH * NH + (size_t)b * NH * NH;

    for (int k = 0; k < NC; k++) {
        // --- publish this chunk's x; prefetch next chunk ---
        if (j < 56) {
            xsg[xslot]      = xpre0;
            xsg[xslot + 64] = xpre1;
            if (k + 1 < NC) {
                xpre0 = xb[(size_t)(k + 1) * (TC * NI) + j];
                xpre1 = xb[(size_t)(k + 1) * (TC * NI) + 56 + j];
            }
        }
        gbar(g);   // bar 1: x visible

        // === Phase B: 16 steps of gates, barrier-free ===
        float vA[TC];
#pragma unroll
        for (int t = 0; t < TC; t++) {
            const float4* xp4 = (const float4*)(xsg + t * 8);
            float4 xa = xp4[0], xb4 = xp4[1];
            float xv[NI] = {xa.x, xa.y, xa.z, xa.w, xb4.x, xb4.y, xb4.z};
            u64 aqk = bqk, avi = bvi, afo = bfo;
            float Sq = bsq;
#pragma unroll
            for (int i = 0; i < NI; i++) {
                u64 x2 = pk2(xv[i], xv[i]);
                aqk = fma2(x2, wqk[i], aqk);
                avi = fma2(x2, wvi[i], avi);
                afo = fma2(x2, wfo[i], afo);
                Sq  = fmaf(xv[i], wsq[i], Sq);
            }
            float q, kk, v, ipre, fpre, opre;
            upk2(aqk, q, kk);
            upk2(avi, v, ipre);
            upk2(afo, fpre, opre);
            float ik = ex2f(ipre) * kk;             // i = exp: log2e folded
            float f  = rcpf(1.f + ex2f(fpre));      // sigmoid: -log2e folded
            float o  = fmaf(tanhap(opre), 0.5f, 0.5f);
            F    *= f;
            Ftot *= f;
            nv    = f * nv + ik;
            a_s[t * NH + j] = ik * rcpf(F);         // a  = ik / F
            q_s[t * NH + j] = F * q;                // q~ = F * q
            od_s[t * NH + j] = pk2(o, rcpf(fmaxf(nv * Sq, 1.f)));   // (o, rden)
            vA[t] = v;
        }
        Fsh[j] = F;
        F = 1.f;   // chunk-end rescale resets the basis
        gbar(g);   // bar 2: a/q/od/Fsh visible

        // === Phase C: 16 steps of C-update + num + h, barrier-free ===
        float* oh = outh + (size_t)k * TC * NH + j;
#pragma unroll
        for (int t = 0; t < TC; t++) {
            const double2* aP = (const double2*)(a_s + t * NH);
            const double2* qP = (const double2*)(q_s + t * NH);
            const u64 v2 = pk2(vA[t], vA[t]);
            float o_, rd_;
            upk2(od_s[t * NH + j], o_, rd_);
            u64 numA = 0ull, numB = 0ull;   // bit pattern 0 == (+0.f,+0.f)
#pragma unroll
            for (int gg = 0; gg < 16; gg++) {
                double2 ad = aP[gg], qd = qP[gg];
                u64 aA = __double_as_longlong(ad.x), aB = __double_as_longlong(ad.y);
                u64 qA = __double_as_longlong(qd.x), qB = __double_as_longlong(qd.y);
                Creg[2 * gg]     = fma2(aA, v2, Creg[2 * gg]);
                numA             = fma2(Creg[2 * gg], qA, numA);
                Creg[2 * gg + 1] = fma2(aB, v2, Creg[2 * gg + 1]);
                numB             = fma2(Creg[2 * gg + 1], qB, numB);
            }
            float nlo, nhi;
            upk2(add2(numA, numB), nlo, nhi);
            oh[t * NH] = o_ * tanhap((nlo + nhi) * rd_);
        }

        // --- chunk-end rescale: C~ <- F (x)col C~ ---
        {
            const double2* FP = (const double2*)Fsh;
#pragma unroll
            for (int gg = 0; gg < 16; gg++) {
                double2 Fd = FP[gg];
                Creg[2 * gg]     = mul2(__double_as_longlong(Fd.x), Creg[2 * gg]);
                Creg[2 * gg + 1] = mul2(__double_as_longlong(Fd.y), Creg[2 * gg + 1]);
            }
        }
        gbar(g);   // bar 3: chunk done; safe for next chunk's smem writes
    }

    // --- final C (last rescale restored true basis) ---
    {
        double2* cp = (double2*)(outC + (size_t)j * NH);
#pragma unroll
        for (int gg = 0; gg < 16; gg++) {
            double2 d;
            d.x = __longlong_as_double(Creg[2 * gg]);
            d.y = __longlong_as_double(Creg[2 * gg + 1]);
            cp[gg] = d;
        }
    }

    // --- final n: n[r,c] = Ftot[c]*n0[r,c] + m[c] ---
    a_s[j] = Ftot;
    q_s[j] = nv;
    gbar(g);
    {
        const float4* n0p = (const float4*)(n0 + (size_t)b * NH * NH + (size_t)j * NH);
        float4*       np  = (float4*)(outN + (size_t)j * NH);
        const float4* Fp  = (const float4*)a_s;
        const float4* mp  = (const float4*)q_s;
#pragma unroll
        for (int gg = 0; gg < 16; gg++) {
            float4 aa = n0p[gg], Fv = Fp[gg], m = mp[gg];
            float4 ro;
            ro.x = Fv.x * aa.x + m.x;
            ro.y = Fv.y * aa.y + m.y;
            ro.z = Fv.z * aa.z + m.z;
            ro.w = Fv.w * aa.w + m.w;
            np[gg] = ro;
        }
    }
}

extern "C" void kernel_launch(void* const* d_in, const int* in_sizes, int n_in,
                              void* d_out, int out_size)
{
    cudaFuncSetAttribute(mlstm_kernel,
                         cudaFuncAttributeMaxDynamicSharedMemorySize, SMEM_BYTES);
    mlstm_kernel<<<NGRID, NTH, SMEM_BYTES>>>(
        (const float*)d_in[0],  (const float*)d_in[1],  (const float*)d_in[2],
        (const float*)d_in[3],  (const float*)d_in[4],
        (const float*)d_in[5],  (const float*)d_in[6],
        (const float*)d_in[7],  (const float*)d_in[8],
        (const float*)d_in[9],  (const float*)d_in[10],
        (const float*)d_in[11], (const float*)d_in[12],
        (const float*)d_in[13], (const float*)d_in[14],
        (float*)d_out);
}

// round 17
// speedup vs baseline: 1.0939x; 1.0939x over previous
#include <cuda_runtime.h>

// mLSTM cell: B=512, T=256, I=7, H=64, fp32.
// Grid 128 x block 256: 4 independent batches ("groups" of 64 threads = 2
// warps) per CTA. WARP-SPECIALIZED within each group:
//   gate  warp: channels (2l,2l+1) packed f32x2 gates; produces a/q~/v/(o,rd)
//               for a whole Tc=8 chunk into double-buffered smem; x via LDG.
//   state warp: thread owns rows (2l,2l+1) of decay-factored C~ as 64 u64
//               pairs; consumes a chunk barrier-free. Each a/q~ load serves
//               TWO rows -> per-SM LDS instruction count ~halved.
// REGISTER UNION: one statically-indexed u64 R[64] holds C~ rows (state) or
// packed weights+F/Ftot/nv (gate) -> ~175 regs instead of 255 (the R13-R15
// wall), restoring ptxas scheduling headroom.
// State warps are CTA warps {0,2,5,7} -> each SMSP gets 1 state + 1 gate warp.
// ONE named barrier per chunk (producer/consumer, double-buffered).
// Factored state: C = F (per-col) * C~ ; C~ += a (x) v, a = ik/F;
// num[r] = sum_c q~[c]*C~[r,c], q~ = F*q (exact). Rescale at chunk end.
// Transcendentals folded: i=ex2(log2e*z), f=rcp(1+ex2(-log2e*z)),
// o=0.5*tanh+0.5, h-tanh=tanh.approx, den via rcp.
// Sq(t)=sum_r q_t[r] as a linear form (row-summed Wq,bq, gate-warp butterfly).
// n row-uniform (n0==0): n[r,c] = Ftot[c]*n0[r,c] + m[c] (general form kept).

#define NB 512
#define NT 256
#define NI 7
#define NH 64
#define GROUPS 4
#define NTH 256
#define NGRID 128
#define TC 8
#define NC (NT / TC)     // 32 chunks
#define L2E 1.4426950408889634f

typedef unsigned long long u64;

// dynamic smem layout (floats)
#define GSZ     (2 * TC * NH)                 // per-group a/q/v floats (1024)
#define OFF_A   0
#define OFF_Q   (OFF_A + GROUPS * GSZ)
#define OFF_V   (OFF_Q + GROUPS * GSZ)
#define OFF_OD  (OFF_V + GROUPS * GSZ)        // (o,rd) = 2 floats per row
#define OFF_FSH (OFF_OD + GROUPS * GSZ * 2)
#define SMEM_FLOATS (OFF_FSH + GROUPS * 2 * NH)
#define SMEM_BYTES  (SMEM_FLOATS * 4)

__device__ __forceinline__ u64 pk2(float lo, float hi) {
    u64 r; asm("mov.b64 %0, {%1,%2};" : "=l"(r) : "f"(lo), "f"(hi)); return r;
}
__device__ __forceinline__ void upk2(u64 a, float& lo, float& hi) {
    asm("mov.b64 {%0,%1}, %2;" : "=f"(lo), "=f"(hi) : "l"(a));
}
__device__ __forceinline__ u64 fma2(u64 a, u64 b, u64 c) {
    u64 d; asm("fma.rn.f32x2 %0, %1, %2, %3;" : "=l"(d) : "l"(a), "l"(b), "l"(c)); return d;
}
__device__ __forceinline__ u64 mul2(u64 a, u64 b) {
    u64 d; asm("mul.rn.f32x2 %0, %1, %2;" : "=l"(d) : "l"(a), "l"(b)); return d;
}
__device__ __forceinline__ u64 add2(u64 a, u64 b) {
    u64 d; asm("add.rn.f32x2 %0, %1, %2;" : "=l"(d) : "l"(a), "l"(b)); return d;
}
__device__ __forceinline__ float ex2f(float a)  { float r; asm("ex2.approx.f32 %0, %1;"  : "=f"(r) : "f"(a)); return r; }
__device__ __forceinline__ float rcpf(float a)  { float r; asm("rcp.approx.f32 %0, %1;"  : "=f"(r) : "f"(a)); return r; }
__device__ __forceinline__ float tanhap(float a){ float r; asm("tanh.approx.f32 %0, %1;" : "=f"(r) : "f"(a)); return r; }
__device__ __forceinline__ void gbar(int g) {
    asm volatile("bar.sync %0, 64;" :: "r"(g + 1) : "memory");
}
#define D2L(x) __longlong_as_double
#define L2D(x) __double_as_longlong(x)

__global__ __launch_bounds__(NTH) void mlstm_kernel(
    const float* __restrict__ x,  const float* __restrict__ C0, const float* __restrict__ n0,
    const float* __restrict__ Wq, const float* __restrict__ bq,
    const float* __restrict__ Wk, const float* __restrict__ bk,
    const float* __restrict__ Wv, const float* __restrict__ bv,
    const float* __restrict__ Wi, const float* __restrict__ bi,
    const float* __restrict__ Wf, const float* __restrict__ bf,
    const float* __restrict__ Wo, const float* __restrict__ bo,
    float* __restrict__ out)
{
    extern __shared__ __align__(16) float smem[];
    const int tid = threadIdx.x;
    const int g = tid >> 6;          // group (batch slot) 0..3
    const int w = (tid >> 5) & 1;    // warp within group
    const int l = tid & 31;          // lane
    const int b = blockIdx.x * GROUPS + g;
    // state warps on CTA warps {0,2,5,7} -> one per SMSP
    const bool isState = (g < 2) ? (w == 0) : (w == 1);
    const int c0 = 2 * l, c1 = 2 * l + 1;   // channel/row pair owned

    float* aG   = smem + OFF_A   + g * GSZ;
    float* qG   = smem + OFF_Q   + g * GSZ;
    float* vG   = smem + OFF_V   + g * GSZ;
    float* odG  = smem + OFF_OD  + g * GSZ * 2;
    float* FshG = smem + OFF_FSH + g * (2 * NH);

    const float* xb = x + (size_t)b * NT * NI;

    // Register union: state = C~ rows (R[0..31]=row c0, R[32..63]=row c1);
    // gate = weights R[0..41], biases R[42..47], F=R[48], Ftot=R[49], nv=R[50].
    u64 R[64];
    float wsq[NI], bsq;

    if (!isState) {
        #pragma unroll
        for (int i = 0; i < NI; i++) {
            R[i]      = pk2(Wq[c0*NI+i],            Wq[c1*NI+i]);
            R[7 + i]  = pk2(0.125f*Wk[c0*NI+i],     0.125f*Wk[c1*NI+i]);
            R[14 + i] = pk2(Wv[c0*NI+i],            Wv[c1*NI+i]);
            R[21 + i] = pk2(L2E*Wi[c0*NI+i],        L2E*Wi[c1*NI+i]);
            R[28 + i] = pk2(-L2E*Wf[c0*NI+i],       -L2E*Wf[c1*NI+i]);
            R[35 + i] = pk2(0.5f*Wo[c0*NI+i],       0.5f*Wo[c1*NI+i]);
        }
        R[42] = pk2(bq[c0], bq[c1]);
        R[43] = pk2(0.125f*bk[c0], 0.125f*bk[c1]);
        R[44] = pk2(bv[c0], bv[c1]);
        R[45] = pk2(L2E*bi[c0], L2E*bi[c1]);
        R[46] = pk2(-L2E*bf[c0], -L2E*bf[c1]);
        R[47] = pk2(0.5f*bo[c0], 0.5f*bo[c1]);
        // row-sum of Wq/bq over all 64 channels: in-warp butterfly
        float p[8];
        #pragma unroll
        for (int i = 0; i < NI; i++) p[i] = Wq[c0*NI+i] + Wq[c1*NI+i];
        p[7] = bq[c0] + bq[c1];
        #pragma unroll
        for (int off = 16; off; off >>= 1)
            #pragma unroll
            for (int i = 0; i < 8; i++)
                p[i] += __shfl_xor_sync(0xffffffffu, p[i], off);
        #pragma unroll
        for (int i = 0; i < NI; i++) wsq[i] = p[i];
        bsq = p[7];
        R[48] = pk2(1.f, 1.f);   // F (chunk-local)
        R[49] = pk2(1.f, 1.f);   // Ftot
        R[50] = 0ull;            // nv  (+0,+0)
    } else {
        const double2* cp0 = (const double2*)(C0 + (size_t)b*NH*NH + (size_t)c0*NH);
        const double2* cp1 = (const double2*)(C0 + (size_t)b*NH*NH + (size_t)c1*NH);
        #pragma unroll
        for (int gg = 0; gg < 16; gg++) {
            double2 d0 = cp0[gg], d1 = cp1[gg];
            R[2*gg]      = L2D(d0.x);  R[2*gg+1]   = L2D(d0.y);
            R[32+2*gg]   = L2D(d1.x);  R[33+2*gg]  = L2D(d1.y);
        }
    }

    float* outh = out + (size_t)b * NT * NH;
    float* outC = out + (size_t)NB * NT * NH + (size_t)b * NH * NH;
    float* outN = out + (size_t)NB * NT * NH + (size_t)NB * NH * NH + (size_t)b * NH * NH;

    // ---- gate warp: produce chunk m into buffer m&1 ----
    auto produce = [&](int m) {
        const int bu = m & 1;
        float* aS  = aG  + bu * (TC * NH);
        float* qS  = qG  + bu * (TC * NH);
        float* vS  = vG  + bu * (TC * NH);
        float* odS = odG + bu * (TC * NH * 2);
        #pragma unroll
        for (int t = 0; t < TC; t++) {
            const float* xt = xb + (size_t)(m * TC + t) * NI;
            float xv[NI];
            #pragma unroll
            for (int i = 0; i < NI; i++) xv[i] = __ldg(xt + i);
            u64 aq = R[42], ak = R[43], av = R[44], ai = R[45], af = R[46], ao = R[47];
            float Sq = bsq;
            #pragma unroll
            for (int i = 0; i < NI; i++) {
                u64 x2 = pk2(xv[i], xv[i]);
                aq = fma2(x2, R[i],      aq);
                ak = fma2(x2, R[7 + i],  ak);
                av = fma2(x2, R[14 + i], av);
                ai = fma2(x2, R[21 + i], ai);
                af = fma2(x2, R[28 + i], af);
                ao = fma2(x2, R[35 + i], ao);
                Sq = fmaf(xv[i], wsq[i], Sq);
            }
            float q0,q1,k0,k1,v0,v1,ip0,ip1,fp0,fp1,op0,op1;
            upk2(aq, q0, q1); upk2(ak, k0, k1); upk2(av, v0, v1);
            upk2(ai, ip0, ip1); upk2(af, fp0, fp1); upk2(ao, op0, op1);
            float ik0 = ex2f(ip0) * k0,          ik1 = ex2f(ip1) * k1;
            float f0  = rcpf(1.f + ex2f(fp0)),   f1  = rcpf(1.f + ex2f(fp1));
            float o0  = fmaf(tanhap(op0), 0.5f, 0.5f);
            float o1  = fmaf(tanhap(op1), 0.5f, 0.5f);
            u64 f2 = pk2(f0, f1), ik2 = pk2(ik0, ik1);
            R[48] = mul2(R[48], f2);
            R[49] = mul2(R[49], f2);
            R[50] = fma2(f2, R[50], ik2);
            float F0, F1; upk2(R[48], F0, F1);
            u64 a2  = mul2(ik2, pk2(rcpf(F0), rcpf(F1)));   // a  = ik / F
            u64 qt2 = mul2(R[48], pk2(q0, q1));             // q~ = F * q
            float n0v, n1v; upk2(R[50], n0v, n1v);
            float rd0 = rcpf(fmaxf(n0v * Sq, 1.f));
            float rd1 = rcpf(fmaxf(n1v * Sq, 1.f));
            *(u64*)(aS + t * NH + c0) = a2;
            *(u64*)(qS + t * NH + c0) = qt2;
            *(u64*)(vS + t * NH + c0) = pk2(v0, v1);
            float4 odv; odv.x = o0; odv.y = rd0; odv.z = o1; odv.w = rd1;
            *(float4*)(odS + t * NH * 2 + 4 * l) = odv;
        }
        *(u64*)(FshG + bu * NH + c0) = R[48];
        R[48] = pk2(1.f, 1.f);   // rescale resets chunk-local basis
    };

    // ---- state warp: consume chunk k from buffer k&1 ----
    auto consume = [&](int k) {
        const int bu = k & 1;
        const float* aS  = aG  + bu * (TC * NH);
        const float* qS  = qG  + bu * (TC * NH);
        const float* vS  = vG  + bu * (TC * NH);
        const float* odS = odG + bu * (TC * NH * 2);
        #pragma unroll
        for (int t = 0; t < TC; t++) {
            const double2* aP = (const double2*)(aS + t * NH);
            const double2* qP = (const double2*)(qS + t * NH);
            float v0, v1; upk2(*(const u64*)(vS + t * NH + c0), v0, v1);
            const u64 v20 = pk2(v0, v0), v21 = pk2(v1, v1);
            u64 nA0 = 0ull, nB0 = 0ull, nA1 = 0ull, nB1 = 0ull;
            #pragma unroll
            for (int gg = 0; gg < 16; gg++) {
                double2 ad = aP[gg], qd = qP[gg];
                u64 aA = L2D(ad.x), aB = L2D(ad.y);
                u64 qA = L2D(qd.x), qB = L2D(qd.y);
                R[2*gg]    = fma2(aA, v20, R[2*gg]);     nA0 = fma2(R[2*gg],    qA, nA0);
                R[32+2*gg] = fma2(aA, v21, R[32+2*gg]);  nA1 = fma2(R[32+2*gg], qA, nA1);
                R[2*gg+1]  = fma2(aB, v20, R[2*gg+1]);   nB0 = fma2(R[2*gg+1],  qB, nB0);
                R[33+2*gg] = fma2(aB, v21, R[33+2*gg]);  nB1 = fma2(R[33+2*gg], qB, nB1);
            }
            float4 odv = *(const float4*)(odS + t * NH * 2 + 4 * l);
            float lo, hi;
            upk2(add2(nA0, nB0), lo, hi);
            float h0 = odv.x * tanhap((lo + hi) * odv.y);
            upk2(add2(nA1, nB1), lo, hi);
            float h1 = odv.z * tanhap((lo + hi) * odv.w);
            *(u64*)(outh + (size_t)(k * TC + t) * NH + c0) = pk2(h0, h1);
        }
        // chunk-end rescale: C~ <- F (x)col C~
        const double2* FP = (const double2*)(FshG + bu * NH);
        #pragma unroll
        for (int gg = 0; gg < 16; gg++) {
            double2 Fd = FP[gg];
            u64 FA = L2D(Fd.x), FB = L2D(Fd.y);
            R[2*gg]    = mul2(FA, R[2*gg]);    R[32+2*gg] = mul2(FA, R[32+2*gg]);
            R[2*gg+1]  = mul2(FB, R[2*gg+1]); R[33+2*gg] = mul2(FB, R[33+2*gg]);
        }
    };

    // ---- pipeline: gate produces k+1 while state consumes k ----
    if (!isState) produce(0);
    gbar(g);
#pragma unroll 1
    for (int k = 0; k < NC; k++) {
        if (!isState) { if (k + 1 < NC) produce(k + 1); }
        else consume(k);
        gbar(g);
    }

    // ---- epilogue ----
    if (!isState) {
        *(u64*)(aG + c0) = R[49];   // Ftot pair
        *(u64*)(qG + c0) = R[50];   // nv (m) pair
    } else {
        // final C (last rescale restored true basis)
        double2* cp0 = (double2*)(outC + (size_t)c0 * NH);
        double2* cp1 = (double2*)(outC + (size_t)c1 * NH);
        #pragma unroll
        for (int gg = 0; gg < 16; gg++) {
            double2 d0, d1;
            d0.x = __longlong_as_double(R[2*gg]);
            d0.y = __longlong_as_double(R[2*gg+1]);
            d1.x = __longlong_as_double(R[32+2*gg]);
            d1.y = __longlong_as_double(R[33+2*gg]);
            cp0[gg] = d0; cp1[gg] = d1;
        }
    }
    gbar(g);
    // final n: n[r,c] = Ftot[c]*n0[r,c] + m[c]; one row per group thread
    {
        const int jg = tid & 63;
        const float4* n0p = (const float4*)(n0 + (size_t)b * NH * NH + (size_t)jg * NH);
        float4*       np  = (float4*)(outN + (size_t)jg * NH);
        const float4* Fp  = (const float4*)aG;
        const float4* mp  = (const float4*)qG;
        #pragma unroll
        for (int gg = 0; gg < 16; gg++) {
            float4 aa = n0p[gg], Fv = Fp[gg], m = mp[gg];
            float4 ro;
            ro.x = Fv.x * aa.x + m.x;
            ro.y = Fv.y * aa.y + m.y;
            ro.z = Fv.z * aa.z + m.z;
            ro.w = Fv.w * aa.w + m.w;
            np[gg] = ro;
        }
    }
}

extern "C" void kernel_launch(void* const* d_in, const int* in_sizes, int n_in,
                              void* d_out, int out_size)
{
    cudaFuncSetAttribute(mlstm_kernel,
                         cudaFuncAttributeMaxDynamicSharedMemorySize, SMEM_BYTES);
    mlstm_kernel<<<NGRID, NTH, SMEM_BYTES>>>(
        (const float*)d_in[0],  (const float*)d_in[1],  (const float*)d_in[2],
        (const float*)d_in[3],  (const float*)d_in[4],
        (const float*)d_in[5],  (const float*)d_in[6],
        (const float*)d_in[7],  (const float*)d_in[8],
        (const float*)d_in[9],  (const float*)d_in[10],
        (const float*)d_in[11], (const float*)d_in[12],
        (const float*)d_in[13], (const float*)d_in[14],
        (float*)d_out);
}